// round 14
// baseline (speedup 1.0000x reference)
#include <cuda_runtime.h>

#define T_DIM 4096
#define B_DIM 64
#define F_DIM 64
#define CS    64               // output chunk size
#define WU    40               // warm-up steps; transient err at first output is WU-INDEPENDENT
#define TS_MIN 200             // first warm chunk must have t0>=256 (err A*om^(t0-56) <= ~0.3)
#define NC    (T_DIM / CS)     // 64 chunks
#define LAG   25
#define NTOT  ((size_t)B_DIM * T_DIM * F_DIM)   // 16777216

#define ALPHA (2.0f / 26.0f)
#define OM    (24.0f / 26.0f)

// checked step: exact-path (t can be < 192 where the adjust factor matters)
__device__ __forceinline__ void estep(float2& e, const float2 xv, int t) {
    e.x = fmaf(OM, e.x, ALPHA * xv.x);
    e.y = fmaf(OM, e.y, ALPHA * xv.y);
    if (t < 192) {             // for t >= 166, om^(t+1) underflows below fp32 ulp of 1
        float w  = 1.0f - __powf(OM, (float)(t + 1));
        float iw = 1.0f / fmaxf(w, 1e-10f);
        e.x *= iw; e.y *= iw;
    }
}

// fast step: warm path only (all t >= 201, adjust factor == 1 in fp32)
__device__ __forceinline__ void estep_fast(float2& e, const float2 xv) {
    e.x = fmaf(OM, e.x, ALPHA * xv.x);
    e.y = fmaf(OM, e.y, ALPHA * xv.y);
}

__device__ __forceinline__ void writeout(float* __restrict__ out, size_t pos,
                                         const float2 e, const float2 lag) {
    float2 s;
    s.x = e.x - lag.x; s.y = e.y - lag.y;
    float2 ab, bl, bt;
    ab.x = (s.x >  15.0f) ? 1.0f : 0.0f;
    ab.y = (s.y >  15.0f) ? 1.0f : 0.0f;
    bl.x = (s.x < -15.0f) ? 1.0f : 0.0f;
    bl.y = (s.y < -15.0f) ? 1.0f : 0.0f;
    bt.x = 1.0f - ab.x - bl.x;
    bt.y = 1.0f - ab.y - bl.y;
    __stcs((float2*)(out +            pos), e);
    __stcs((float2*)(out + NTOT     + pos), s);
    __stcs((float2*)(out + 2 * NTOT + pos), ab);
    __stcs((float2*)(out + 3 * NTOT + pos), bl);
    __stcs((float2*)(out + 4 * NTOT + pos), bt);
}

__global__ void __launch_bounds__(128, 7)
ema_slope_filter_kernel(const float* __restrict__ x, float* __restrict__ out) {
    int gtid = blockIdx.x * blockDim.x + threadIdx.x;
    int f2 = gtid & 31;                 // float2 index along F
    int b  = (gtid >> 5) & 63;
    int c  = gtid >> 11;                // chunk index 0..NC-1

    const float2* xb = (const float2*)(x + (size_t)b * T_DIM * F_DIM) + f2;
    size_t obase = (size_t)b * T_DIM * F_DIM + (size_t)f2 * 2;

    if (c == 0) {
        // exact prefix: t < LAG has lagged = 0; el chain starts stepping at tl = 1
        float2 e  = xb[0];
        float2 el = e;
        float2 z  = make_float2(0.f, 0.f);
        writeout(out, obase, e, z);
        for (int t = 1; t < LAG; ++t) {
            estep(e, xb[(size_t)t * 32], t);
            writeout(out, obase + (size_t)t * F_DIM, e, z);
        }
        for (int t = LAG; t < CS; ++t) {
            estep(e, xb[(size_t)t * 32], t);
            if (t > LAG)                // first el step at tl=1 (el seed IS ema[0])
                estep(el, xb[(size_t)(t - LAG) * 32], t - LAG);
            writeout(out, obase + (size_t)t * F_DIM, e, el);
        }
        return;
    }

    int t0 = c * CS;
    int te = t0 + CS;
    int ts = t0 - WU;

    if (ts < TS_MIN) {
        // ---- EXACT path (c = 1..3): run from t=0 with checked esteps ----
        float2 e = xb[0];
        int t = 1;
        int tsnap = t0 - 1 - LAG;
        #pragma unroll 1
        for (; t + 8 <= tsnap + 1; t += 8) {
            float2 xt[8];
            #pragma unroll
            for (int u = 0; u < 8; ++u) xt[u] = xb[(size_t)(t + u) * 32];
            #pragma unroll
            for (int u = 0; u < 8; ++u) estep(e, xt[u], t + u);
        }
        #pragma unroll 1
        for (; t <= tsnap; ++t) estep(e, xb[(size_t)t * 32], t);

        float2 el = e;
        {
            float2 xt[13];
            #pragma unroll
            for (int u = 0; u < 13; ++u) xt[u] = xb[(size_t)(t + u) * 32];
            #pragma unroll
            for (int u = 0; u < 13; ++u) estep(e, xt[u], t + u);
            t += 13;
            float2 x2[12];
            #pragma unroll
            for (int u = 0; u < 12; ++u) x2[u] = xb[(size_t)(t + u) * 32];
            #pragma unroll
            for (int u = 0; u < 12; ++u) estep(e, x2[u], t + u);
            t += 12;                    // t == t0
        }
        #pragma unroll 1
        for (; t < te; t += 8) {
            float2 xt[8], xl[8];
            #pragma unroll
            for (int u = 0; u < 8; ++u) xt[u] = xb[(size_t)(t + u) * 32];
            #pragma unroll
            for (int u = 0; u < 8; ++u) xl[u] = xb[(size_t)(t + u - LAG) * 32];
            #pragma unroll
            for (int u = 0; u < 8; ++u) {
                estep(e,  xt[u], t + u);
                estep(el, xl[u], t + u - LAG);
                writeout(out, obase + (size_t)(t + u) * F_DIM, e, el);
            }
        }
        return;
    }

    // ---- WARM path: ts >= 200, so every step has t > 192 -> estep_fast ----
    float2 e = xb[(size_t)ts * 32];     // seed; transient decayed per TS_MIN invariant

    int t = ts + 1;
    // phase A: single chain, WU-26 = 14 steps, one batch
    {
        float2 xt[WU - 26];
        #pragma unroll
        for (int u = 0; u < WU - 26; ++u) xt[u] = xb[(size_t)(t + u) * 32];
        #pragma unroll
        for (int u = 0; u < WU - 26; ++u) estep_fast(e, xt[u]);
        t += WU - 26;                   // t == t0 - 25
    }

    float2 el = e;                      // el = ema[t0-1-LAG]

    // phase B: advance e alone the last LAG=25 steps (13 + 12)
    {
        float2 xt[13];
        #pragma unroll
        for (int u = 0; u < 13; ++u) xt[u] = xb[(size_t)(t + u) * 32];
        #pragma unroll
        for (int u = 0; u < 13; ++u) estep_fast(e, xt[u]);
        t += 13;
        float2 x2[12];
        #pragma unroll
        for (int u = 0; u < 12; ++u) x2[u] = xb[(size_t)(t + u) * 32];
        #pragma unroll
        for (int u = 0; u < 12; ++u) estep_fast(e, x2[u]);
        t += 12;                        // t == t0
    }

    // phase C: output, stream-grouped stores (2KB bursts per stream per warp)
    #pragma unroll 1
    for (; t < te; t += 8) {
        float2 xt[8], xl[8];
        #pragma unroll
        for (int u = 0; u < 8; ++u) xt[u] = xb[(size_t)(t + u) * 32];
        #pragma unroll
        for (int u = 0; u < 8; ++u) xl[u] = xb[(size_t)(t + u - LAG) * 32];

        float2 eo[8], so[8];
        #pragma unroll
        for (int u = 0; u < 8; ++u) {
            estep_fast(e,  xt[u]);
            estep_fast(el, xl[u]);
            eo[u] = e;
            so[u] = make_float2(e.x - el.x, e.y - el.y);
        }

        size_t p = obase + (size_t)t * F_DIM;
        #pragma unroll
        for (int u = 0; u < 8; ++u)
            __stcs((float2*)(out + p + (size_t)u * F_DIM), eo[u]);
        #pragma unroll
        for (int u = 0; u < 8; ++u)
            __stcs((float2*)(out + NTOT + p + (size_t)u * F_DIM), so[u]);
        #pragma unroll
        for (int u = 0; u < 8; ++u) {
            float2 ab;
            ab.x = (so[u].x > 15.0f) ? 1.0f : 0.0f;
            ab.y = (so[u].y > 15.0f) ? 1.0f : 0.0f;
            __stcs((float2*)(out + 2 * NTOT + p + (size_t)u * F_DIM), ab);
        }
        #pragma unroll
        for (int u = 0; u < 8; ++u) {
            float2 bl;
            bl.x = (so[u].x < -15.0f) ? 1.0f : 0.0f;
            bl.y = (so[u].y < -15.0f) ? 1.0f : 0.0f;
            __stcs((float2*)(out + 3 * NTOT + p + (size_t)u * F_DIM), bl);
        }
        #pragma unroll
        for (int u = 0; u < 8; ++u) {
            float2 bt;
            bt.x = (so[u].x >= -15.0f && so[u].x <= 15.0f) ? 1.0f : 0.0f;
            bt.y = (so[u].y >= -15.0f && so[u].y <= 15.0f) ? 1.0f : 0.0f;
            __stcs((float2*)(out + 4 * NTOT + p + (size_t)u * F_DIM), bt);
        }
    }
}

extern "C" void kernel_launch(void* const* d_in, const int* in_sizes, int n_in,
                              void* d_out, int out_size) {
    const float* x = (const float*)d_in[0];
    float* out = (float*)d_out;
    int total = 32 * B_DIM * NC;        // 131072 threads
    ema_slope_filter_kernel<<<total / 128, 128>>>(x, out);
}